// round 2
// baseline (speedup 1.0000x reference)
#include <cuda_runtime.h>

// out[b] = -(inp[b,:] . quad)^2 + inp[b,:] . linw + bias
// B = 16384, D = 4096, fp32. Pure streaming-read problem: 256 MiB of inp.
//
// R2 changes vs R1 (53.2us, DRAM 63%):
//  - grid 512 -> 1024 (ROWS_PER_WARP 4 -> 2): R1 was a single under-filled
//    wave (740 block capacity at 5 blocks/SM); now SMs stay saturated.
//  - paired-row inner loop: one smem (q,l) read feeds FMAs of TWO x rows
//    (halves L1/smem traffic per DRAM byte, doubles LDGs in flight per lane).
//  - __ldcs streaming loads for inp (zero reuse -> evict-first, keep weights
//    hot in L2/L1).
//  - __launch_bounds__(256, 6) caps regs so 6 blocks/SM fit.

#ifndef D_DIM
#define D_DIM 4096
#endif

constexpr int THREADS        = 256;   // 8 warps
constexpr int ROWS_PER_WARP  = 2;     // paired in the inner loop
constexpr int WARPS          = THREADS / 32;
constexpr int ROWS_PER_BLOCK = WARPS * ROWS_PER_WARP;  // 16
constexpr int D4             = D_DIM / 4;              // 1024 float4 per row
constexpr int F4_PER_LANE    = D4 / 32;                // 32 float4 per lane per row

__global__ __launch_bounds__(THREADS, 6)
void skinny_quad_kernel(const float* __restrict__ inp,
                        const float* __restrict__ quad,
                        const float* __restrict__ linw,
                        const float* __restrict__ linb,
                        float* __restrict__ out,
                        int B)
{
    __shared__ float4 s_wq[D4];
    __shared__ float4 s_wl[D4];

    const int tid  = threadIdx.x;
    const int lane = tid & 31;
    const int warp = tid >> 5;

    // Stage weights into SMEM (weights are L2-resident; tiny cost per block)
    const float4* gq = reinterpret_cast<const float4*>(quad);
    const float4* gl = reinterpret_cast<const float4*>(linw);
    #pragma unroll
    for (int i = tid; i < D4; i += THREADS) {
        s_wq[i] = gq[i];
        s_wl[i] = gl[i];
    }
    const float bias = __ldg(linb);
    __syncthreads();

    const int row0 = blockIdx.x * ROWS_PER_BLOCK + warp * ROWS_PER_WARP;
    if (row0 >= B) return;

    const float4* __restrict__ xr0 =
        reinterpret_cast<const float4*>(inp + (size_t)row0 * D_DIM);
    const float4* __restrict__ xr1 =
        reinterpret_cast<const float4*>(inp + (size_t)(row0 + 1) * D_DIM);

    float sq0 = 0.f, sl0 = 0.f;
    float sq1 = 0.f, sl1 = 0.f;

    #pragma unroll 4
    for (int i = 0; i < F4_PER_LANE; ++i) {
        const int idx = lane + i * 32;          // lanes -> consecutive float4
        const float4 x0 = __ldcs(&xr0[idx]);    // streaming: evict-first
        const float4 x1 = __ldcs(&xr1[idx]);
        const float4 q  = s_wq[idx];
        const float4 l  = s_wl[idx];

        sq0 = fmaf(x0.x, q.x, sq0);
        sq0 = fmaf(x0.y, q.y, sq0);
        sq0 = fmaf(x0.z, q.z, sq0);
        sq0 = fmaf(x0.w, q.w, sq0);
        sl0 = fmaf(x0.x, l.x, sl0);
        sl0 = fmaf(x0.y, l.y, sl0);
        sl0 = fmaf(x0.z, l.z, sl0);
        sl0 = fmaf(x0.w, l.w, sl0);

        sq1 = fmaf(x1.x, q.x, sq1);
        sq1 = fmaf(x1.y, q.y, sq1);
        sq1 = fmaf(x1.z, q.z, sq1);
        sq1 = fmaf(x1.w, q.w, sq1);
        sl1 = fmaf(x1.x, l.x, sl1);
        sl1 = fmaf(x1.y, l.y, sl1);
        sl1 = fmaf(x1.z, l.z, sl1);
        sl1 = fmaf(x1.w, l.w, sl1);
    }

    // warp reduction of the 4 partials
    #pragma unroll
    for (int off = 16; off > 0; off >>= 1) {
        sq0 += __shfl_down_sync(0xFFFFFFFFu, sq0, off);
        sl0 += __shfl_down_sync(0xFFFFFFFFu, sl0, off);
        sq1 += __shfl_down_sync(0xFFFFFFFFu, sq1, off);
        sl1 += __shfl_down_sync(0xFFFFFFFFu, sl1, off);
    }

    if (lane == 0) {
        out[row0]     = fmaf(-sq0, sq0, sl0 + bias);
        out[row0 + 1] = fmaf(-sq1, sq1, sl1 + bias);
    }
}

extern "C" void kernel_launch(void* const* d_in, const int* in_sizes, int n_in,
                              void* d_out, int out_size)
{
    const float* inp  = (const float*)d_in[0];   // (B, D)
    const float* quad = (const float*)d_in[1];   // (D, 1) contiguous D floats
    const float* linw = (const float*)d_in[2];   // (1, D) contiguous D floats
    const float* linb = (const float*)d_in[3];   // (1,)
    float* out = (float*)d_out;

    const int B = in_sizes[0] / D_DIM;
    const int grid = (B + ROWS_PER_BLOCK - 1) / ROWS_PER_BLOCK;

    skinny_quad_kernel<<<grid, THREADS>>>(inp, quad, linw, linb, out, B);
}

// round 3
// speedup vs baseline: 1.2800x; 1.2800x over previous
#include <cuda_runtime.h>

// out[b] = -(inp[b,:] . quad)^2 + inp[b,:] . linw + bias
// B = 16384, D = 4096, fp32. Pure streaming-read problem: 256 MiB of inp.
//
// R3: exact R1 inner loop (53.2us, DRAM 63%) — single-row stream, unroll 8,
// plain cached float4 LDGs, no launch_bounds cap — with ONLY the grid changed:
// ROWS_PER_WARP 4 -> 2, grid 512 -> 1024. R1 was one under-filled wave
// (512 blocks vs ~740 resident capacity); R2 proved extra warps alone don't
// help if the load stream degrades, so the loop body is untouched.

#ifndef D_DIM
#define D_DIM 4096
#endif

constexpr int THREADS        = 256;   // 8 warps
constexpr int ROWS_PER_WARP  = 2;
constexpr int WARPS          = THREADS / 32;
constexpr int ROWS_PER_BLOCK = WARPS * ROWS_PER_WARP;  // 16
constexpr int D4             = D_DIM / 4;              // 1024 float4 per row
constexpr int F4_PER_LANE    = D4 / 32;                // 32 float4 per lane per row

__global__ __launch_bounds__(THREADS)
void skinny_quad_kernel(const float* __restrict__ inp,
                        const float* __restrict__ quad,
                        const float* __restrict__ linw,
                        const float* __restrict__ linb,
                        float* __restrict__ out,
                        int B)
{
    __shared__ float4 s_wq[D4];
    __shared__ float4 s_wl[D4];

    const int tid  = threadIdx.x;
    const int lane = tid & 31;
    const int warp = tid >> 5;

    // Stage weights into SMEM (L2-resident after first blocks; tiny cost)
    const float4* gq = reinterpret_cast<const float4*>(quad);
    const float4* gl = reinterpret_cast<const float4*>(linw);
    #pragma unroll
    for (int i = tid; i < D4; i += THREADS) {
        s_wq[i] = gq[i];
        s_wl[i] = gl[i];
    }
    const float bias = *linb;
    __syncthreads();

    const int row0 = blockIdx.x * ROWS_PER_BLOCK + warp * ROWS_PER_WARP;

    #pragma unroll
    for (int r = 0; r < ROWS_PER_WARP; ++r) {
        const int row = row0 + r;
        if (row >= B) break;

        const float4* __restrict__ xr =
            reinterpret_cast<const float4*>(inp + (size_t)row * D_DIM);

        float sq = 0.f;
        float sl = 0.f;

        #pragma unroll 8
        for (int i = 0; i < F4_PER_LANE; ++i) {
            const int idx = lane + i * 32;     // lanes -> consecutive float4
            const float4 x = xr[idx];
            const float4 q = s_wq[idx];
            const float4 l = s_wl[idx];
            sq = fmaf(x.x, q.x, sq);
            sq = fmaf(x.y, q.y, sq);
            sq = fmaf(x.z, q.z, sq);
            sq = fmaf(x.w, q.w, sq);
            sl = fmaf(x.x, l.x, sl);
            sl = fmaf(x.y, l.y, sl);
            sl = fmaf(x.z, l.z, sl);
            sl = fmaf(x.w, l.w, sl);
        }

        // warp reduction of the (sq, sl) pair
        #pragma unroll
        for (int off = 16; off > 0; off >>= 1) {
            sq += __shfl_down_sync(0xFFFFFFFFu, sq, off);
            sl += __shfl_down_sync(0xFFFFFFFFu, sl, off);
        }

        if (lane == 0) {
            out[row] = fmaf(-sq, sq, sl + bias);
        }
    }
}

extern "C" void kernel_launch(void* const* d_in, const int* in_sizes, int n_in,
                              void* d_out, int out_size)
{
    const float* inp  = (const float*)d_in[0];   // (B, D)
    const float* quad = (const float*)d_in[1];   // (D, 1) contiguous D floats
    const float* linw = (const float*)d_in[2];   // (1, D) contiguous D floats
    const float* linb = (const float*)d_in[3];   // (1,)
    float* out = (float*)d_out;

    const int B = in_sizes[0] / D_DIM;
    const int grid = (B + ROWS_PER_BLOCK - 1) / ROWS_PER_BLOCK;

    skinny_quad_kernel<<<grid, THREADS>>>(inp, quad, linw, linb, out, B);
}

// round 4
// speedup vs baseline: 1.4525x; 1.1348x over previous
#include <cuda_runtime.h>

// out[b] = -(inp[b,:] . quad)^2 + inp[b,:] . linw + bias
// B = 16384, D = 4096, fp32. 256 MiB streaming read — HBM-bound.
//
// R4: warp-per-COLUMN-CHUNK layout. Each of 8 warps owns 512 consecutive
// floats of D; its q/l weights live in 32 REGISTERS (loaded once) -> zero
// LDS in the inner loop. The warp streams 16 rows; per row: 4 independent
// LDG.128 + 32 FMA + warp shuffle reduce. Row r+1 loads are independent of
// row r compute -> deep software pipelining / high MLP without smem.
// Per-(row,warp) partials -> 1KB smem -> 16-thread final reduction.

#ifndef D_DIM
#define D_DIM 4096
#endif

constexpr int THREADS        = 256;            // 8 warps
constexpr int WARPS          = THREADS / 32;   // 8
constexpr int F4_PER_LANE    = (D_DIM / WARPS) / 4 / 32;  // 512/4/32 = 4
constexpr int ROWS_PER_BLOCK = 16;

__global__ __launch_bounds__(THREADS)
void skinny_quad_kernel(const float* __restrict__ inp,
                        const float* __restrict__ quad,
                        const float* __restrict__ linw,
                        const float* __restrict__ linb,
                        float* __restrict__ out,
                        int B)
{
    __shared__ float2 s_part[ROWS_PER_BLOCK][WARPS];

    const int tid  = threadIdx.x;
    const int lane = tid & 31;
    const int warp = tid >> 5;

    // warp's column chunk: float4 index base (128 float4 per warp chunk)
    const int cbase = warp * (D_DIM / WARPS / 4);   // warp * 128

    // Load this warp's weights into REGISTERS (once per block)
    const float4* __restrict__ gq = reinterpret_cast<const float4*>(quad) + cbase;
    const float4* __restrict__ gl = reinterpret_cast<const float4*>(linw) + cbase;
    float4 q[F4_PER_LANE], l[F4_PER_LANE];
    #pragma unroll
    for (int i = 0; i < F4_PER_LANE; ++i) {
        q[i] = gq[i * 32 + lane];
        l[i] = gl[i * 32 + lane];
    }

    const int row0 = blockIdx.x * ROWS_PER_BLOCK;

    #pragma unroll 2
    for (int r = 0; r < ROWS_PER_BLOCK; ++r) {
        const float4* __restrict__ xr =
            reinterpret_cast<const float4*>(inp + (size_t)(row0 + r) * D_DIM) + cbase;

        // 4 independent 128-bit loads (2KB contiguous per warp-row)
        float4 x[F4_PER_LANE];
        #pragma unroll
        for (int i = 0; i < F4_PER_LANE; ++i)
            x[i] = xr[i * 32 + lane];

        float sq = 0.f, sl = 0.f;
        #pragma unroll
        for (int i = 0; i < F4_PER_LANE; ++i) {
            sq = fmaf(x[i].x, q[i].x, sq);
            sq = fmaf(x[i].y, q[i].y, sq);
            sq = fmaf(x[i].z, q[i].z, sq);
            sq = fmaf(x[i].w, q[i].w, sq);
            sl = fmaf(x[i].x, l[i].x, sl);
            sl = fmaf(x[i].y, l[i].y, sl);
            sl = fmaf(x[i].z, l[i].z, sl);
            sl = fmaf(x[i].w, l[i].w, sl);
        }

        // warp reduction of the (sq, sl) pair
        #pragma unroll
        for (int off = 16; off > 0; off >>= 1) {
            sq += __shfl_down_sync(0xFFFFFFFFu, sq, off);
            sl += __shfl_down_sync(0xFFFFFFFFu, sl, off);
        }
        if (lane == 0)
            s_part[r][warp] = make_float2(sq, sl);
    }

    __syncthreads();

    // Final cross-warp reduction: one thread per row
    if (tid < ROWS_PER_BLOCK) {
        const float bias = *linb;
        float sq = 0.f, sl = 0.f;
        #pragma unroll
        for (int w = 0; w < WARPS; ++w) {
            const float2 p = s_part[tid][w];
            sq += p.x;
            sl += p.y;
        }
        const int row = row0 + tid;
        if (row < B)
            out[row] = fmaf(-sq, sq, sl + bias);
    }
}

extern "C" void kernel_launch(void* const* d_in, const int* in_sizes, int n_in,
                              void* d_out, int out_size)
{
    const float* inp  = (const float*)d_in[0];   // (B, D)
    const float* quad = (const float*)d_in[1];   // (D, 1) contiguous D floats
    const float* linw = (const float*)d_in[2];   // (1, D) contiguous D floats
    const float* linb = (const float*)d_in[3];   // (1,)
    float* out = (float*)d_out;

    const int B = in_sizes[0] / D_DIM;
    const int grid = (B + ROWS_PER_BLOCK - 1) / ROWS_PER_BLOCK;

    skinny_quad_kernel<<<grid, THREADS>>>(inp, quad, linw, linb, out, B);
}

// round 5
// speedup vs baseline: 1.4545x; 1.0014x over previous
#include <cuda_runtime.h>

// out[b] = -(inp[b,:] . quad)^2 + inp[b,:] . linw + bias
// B = 16384, D = 4096, fp32. 256 MiB streaming read — HBM-bound.
//
// R5 vs R4 (45.1us, DRAM 74%): the per-row 10-shuffle reduction (~130cyc
// dependent SHFL chain) sat between load batches and kept the LSU queue
// from staying full. Now the streaming loop is ONLY: 4 LDG.128 + 32 FMA +
// 1 STS.64 of the per-lane (sq,sl) partial. STS is fire-and-forget, so the
// loop-carried path is just address math -> loads pipeline across rows.
// All reductions happen once per block at the end from 32KB smem.

#ifndef D_DIM
#define D_DIM 4096
#endif

constexpr int THREADS        = 256;            // 8 warps
constexpr int WARPS          = THREADS / 32;   // 8
constexpr int F4_PER_LANE    = (D_DIM / WARPS) / 4 / 32;  // 4
constexpr int ROWS_PER_BLOCK = 16;

__global__ __launch_bounds__(THREADS)
void skinny_quad_kernel(const float* __restrict__ inp,
                        const float* __restrict__ quad,
                        const float* __restrict__ linw,
                        const float* __restrict__ linb,
                        float* __restrict__ out,
                        int B)
{
    // per-lane partials: [row][256 lanes] (float2 = sq, sl) -> 32KB
    __shared__ float2 s_part[ROWS_PER_BLOCK][THREADS];

    const int tid  = threadIdx.x;
    const int lane = tid & 31;
    const int warp = tid >> 5;

    // warp's column chunk: 128 float4 (512 floats)
    const int cbase = warp * (D_DIM / WARPS / 4);

    // Weights in registers, loaded once per block
    const float4* __restrict__ gq = reinterpret_cast<const float4*>(quad) + cbase;
    const float4* __restrict__ gl = reinterpret_cast<const float4*>(linw) + cbase;
    float4 q[F4_PER_LANE], l[F4_PER_LANE];
    #pragma unroll
    for (int i = 0; i < F4_PER_LANE; ++i) {
        q[i] = gq[i * 32 + lane];
        l[i] = gl[i * 32 + lane];
    }

    const int row0 = blockIdx.x * ROWS_PER_BLOCK;

    #pragma unroll 2
    for (int r = 0; r < ROWS_PER_BLOCK; ++r) {
        const float4* __restrict__ xr =
            reinterpret_cast<const float4*>(inp + (size_t)(row0 + r) * D_DIM) + cbase;

        float4 x[F4_PER_LANE];
        #pragma unroll
        for (int i = 0; i < F4_PER_LANE; ++i)
            x[i] = xr[i * 32 + lane];

        float sq = 0.f, sl = 0.f;
        #pragma unroll
        for (int i = 0; i < F4_PER_LANE; ++i) {
            sq = fmaf(x[i].x, q[i].x, sq);
            sq = fmaf(x[i].y, q[i].y, sq);
            sq = fmaf(x[i].z, q[i].z, sq);
            sq = fmaf(x[i].w, q[i].w, sq);
            sl = fmaf(x[i].x, l[i].x, sl);
            sl = fmaf(x[i].y, l[i].y, sl);
            sl = fmaf(x[i].z, l[i].z, sl);
            sl = fmaf(x[i].w, l[i].w, sl);
        }

        // fire-and-forget per-lane partial; no shuffles in the stream loop
        s_part[r][tid] = make_float2(sq, sl);
    }

    __syncthreads();

    // Block-wide reduction: 16 threads per row, each sums 16 partials,
    // then a 4-stage shuffle reduce within the 16-thread subgroup.
    {
        const int row = tid >> 4;        // 0..15
        const int sub = tid & 15;        // 0..15

        float sq = 0.f, sl = 0.f;
        #pragma unroll
        for (int k = 0; k < THREADS / 16; ++k) {
            const float2 p = s_part[row][sub + k * 16];
            sq += p.x;
            sl += p.y;
        }

        #pragma unroll
        for (int off = 8; off > 0; off >>= 1) {
            sq += __shfl_down_sync(0xFFFFFFFFu, sq, off, 16);
            sl += __shfl_down_sync(0xFFFFFFFFu, sl, off, 16);
        }

        if (sub == 0) {
            const int orow = row0 + row;
            if (orow < B) {
                const float bias = *linb;
                out[orow] = fmaf(-sq, sq, sl + bias);
            }
        }
    }
}

extern "C" void kernel_launch(void* const* d_in, const int* in_sizes, int n_in,
                              void* d_out, int out_size)
{
    const float* inp  = (const float*)d_in[0];   // (B, D)
    const float* quad = (const float*)d_in[1];   // (D, 1) contiguous D floats
    const float* linw = (const float*)d_in[2];   // (1, D) contiguous D floats
    const float* linb = (const float*)d_in[3];   // (1,)
    float* out = (float*)d_out;

    const int B = in_sizes[0] / D_DIM;
    const int grid = (B + ROWS_PER_BLOCK - 1) / ROWS_PER_BLOCK;

    skinny_quad_kernel<<<grid, THREADS>>>(inp, quad, linw, linb, out, B);
}